// round 14
// baseline (speedup 1.0000x reference)
#include <cuda_runtime.h>
#include <cuda_fp16.h>
#include <cstdint>

// ---------------------------------------------------------------------------
// Problem constants
// ---------------------------------------------------------------------------
#define NROWS 8192
#define DIM   2048
#define CS    8
#define NT    (NROWS / 128)            // 64 row-tiles of 128
#define NPAIR (NT * (NT + 1) / 2)      // 2080 symmetric tile pairs
#define BK    64
#define KITER (DIM / BK)               // 32
#define NSTAGE 2
#define STAGE_BYTES 16384              // 128 rows x 128 bytes (64 f16)
#define SMEM_BYTES (NSTAGE * STAGE_BYTES * 2)   // 65536: A stages then B stages
#define NCTA_PERSIST 444               // 148 SMs x 3 CTAs

// Scratch (device globals; no allocations allowed)
__device__ __half g_xh[(size_t)NROWS * DIM];          // f16 copy of x (32 MB)
__device__ float g_dap[NROWS];
__device__ unsigned long long g_best[NROWS];          // packed (mono(f32)<<32) | ~idx
__device__ unsigned g_work;                           // persistent work counter

// ---------------------------------------------------------------------------
// helpers
// ---------------------------------------------------------------------------
__device__ __forceinline__ void cp16(uint32_t dst, const void* src) {
    asm volatile("cp.async.cg.shared.global [%0], [%1], 16;\n" :: "r"(dst), "l"(src));
}
__device__ __forceinline__ void ldsm4(uint32_t& r0, uint32_t& r1, uint32_t& r2, uint32_t& r3,
                                      uint32_t a) {
    asm volatile("ldmatrix.sync.aligned.m8n8.x4.shared.b16 {%0,%1,%2,%3}, [%4];"
                 : "=r"(r0), "=r"(r1), "=r"(r2), "=r"(r3) : "r"(a));
}
__device__ __forceinline__ uint32_t smem_u32(const void* p) {
    uint32_t a;
    asm("{ .reg .u64 t; cvta.to.shared.u64 t, %1; cvt.u32.u64 %0, t; }" : "=r"(a) : "l"(p));
    return a;
}
__device__ __forceinline__ unsigned long long packmax(float v, int idx) {
    unsigned fb = __float_as_uint(v);
    unsigned mono = (fb & 0x80000000u) ? ~fb : (fb | 0x80000000u);
    return ((unsigned long long)mono << 32) | (unsigned)(~idx);
}
__device__ __forceinline__ unsigned long long umax64(unsigned long long a, unsigned long long b) {
    return a > b ? a : b;
}
// decode linear pair index -> (ti, tj), ti <= tj
__device__ __forceinline__ void decode_pair(int t, int& ti, int& tj) {
    int len = NT;
    ti = 0;
    while (t >= len) { t -= len; len--; ti++; }
    tj = ti + t;
}

// ---------------------------------------------------------------------------
// Kernel 1: chunk centers -> d_ap, fp32 -> f16 conversion, resets
// 512 threads, loop-free (DIM/4 == 512)
// ---------------------------------------------------------------------------
__global__ __launch_bounds__(512) void prep_kernel(const float* __restrict__ x, float* out) {
    const int r0 = blockIdx.x * CS;
    const int d  = threadIdx.x;                    // 0..511 == DIM/4 columns

    if (threadIdx.x < CS) g_best[r0 + threadIdx.x] = 0ULL;
    if (blockIdx.x == 0 && threadIdx.x == 0) { out[0] = 0.0f; g_work = NCTA_PERSIST; }

    float acc[CS];
    float4 v[CS];
    float4 s = make_float4(0.f, 0.f, 0.f, 0.f);
#pragma unroll
    for (int k = 0; k < CS; k++) {
        v[k] = reinterpret_cast<const float4*>(x + (size_t)(r0 + k) * DIM)[d];
        s.x += v[k].x; s.y += v[k].y; s.z += v[k].z; s.w += v[k].w;
    }
    const float4 c = make_float4(s.x * 0.125f, s.y * 0.125f, s.z * 0.125f, s.w * 0.125f);
#pragma unroll
    for (int k = 0; k < CS; k++) {
        acc[k] = fabsf(v[k].x - c.x) + fabsf(v[k].y - c.y)
               + fabsf(v[k].z - c.z) + fabsf(v[k].w - c.w);
        __half2 lo = __floats2half2_rn(v[k].x, v[k].y);
        __half2 hi = __floats2half2_rn(v[k].z, v[k].w);
        uint2 u;
        u.x = *reinterpret_cast<unsigned*>(&lo);
        u.y = *reinterpret_cast<unsigned*>(&hi);
        *reinterpret_cast<uint2*>(&g_xh[(size_t)(r0 + k) * DIM + d * 4]) = u;
    }

    __shared__ float sred[CS];
    if (threadIdx.x < CS) sred[threadIdx.x] = 0.0f;
    __syncthreads();
#pragma unroll
    for (int k = 0; k < CS; k++)
#pragma unroll
        for (int o = 16; o > 0; o >>= 1)
            acc[k] += __shfl_xor_sync(0xFFFFFFFFu, acc[k], o);
    if ((threadIdx.x & 31) == 0)
#pragma unroll
        for (int k = 0; k < CS; k++) atomicAdd(&sred[k], acc[k]);
    __syncthreads();
    if (threadIdx.x < CS)
        g_dap[r0 + threadIdx.x] = 0.5f * sred[threadIdx.x] / (float)DIM;
}

// ---------------------------------------------------------------------------
// Kernel 2: PERSISTENT symmetric sim-GEMM (f16 in, f16 acc), 128x128 tile
// pairs ti<=tj pulled via work-stealing counter; 2-stage cp.async double
// buffer; next tile's stage-0 loads overlap current epilogue.
// grid = NCTA_PERSIST, block = 256 (8 warps: 2(M) x 4(N), each 64x32)
// ---------------------------------------------------------------------------
__global__ __launch_bounds__(256, 3) void simgemm_kernel() {
    extern __shared__ char smem[];
    __shared__ unsigned long long rowbest_s[128];
    __shared__ unsigned long long colbest_s[128];
    __shared__ int s_pair;

    const uint32_t sb = smem_u32(smem);
    const int tid  = threadIdx.x;
    const int lane = tid & 31;
    const int warp = tid >> 5;
    const int wr   = warp >> 2;        // 0..1 -> M offset wr*64
    const int wc   = warp & 3;         // 0..3 -> N offset wc*32
    const int qr   = lane >> 2;        // 0..7
    const int qc   = (lane & 3) * 2;   // 0,2,4,6

    if (tid < 128) { rowbest_s[tid] = 0ULL; colbest_s[tid] = 0ULL; }

    // per-lane ldmatrix addressing constants
    const int am    = wr * 64 + (lane & 15);               // A row for this lane
    const uint32_t aRow = (uint32_t)am * 128;
    const uint32_t aXor = (uint32_t)((am & 7) << 4);
    const uint32_t aKh  = (uint32_t)((lane >> 4) * 16);    // k-half byte offset
    const int bn    = wc * 32 + (lane & 7) + ((lane >> 4) << 3);  // B (n) row
    const uint32_t bRow = (uint32_t)bn * 128;
    const uint32_t bXor = (uint32_t)((bn & 7) << 4);
    const uint32_t bKh  = (uint32_t)(((lane >> 3) & 1) * 16);

    // cp.async destination addressing (per thread, 4 vectors of 16B)
    // idx = tid + v*256 -> row = idx>>3, col byte = (idx&7)*16
    uint32_t dsw[4];
    const __half* goff[4];
#pragma unroll
    for (int v = 0; v < 4; v++) {
        const int idx = tid + v * 256;
        const int row = idx >> 3;
        const int c8  = (idx & 7) * 8;
        const uint32_t off = row * 128 + c8 * 2;
        dsw[v]  = off ^ ((off >> 3) & 0x70);
        goff[v] = g_xh + (size_t)row * DIM + c8;           // add row-tile*128*DIM + k0
    }

    // current tile state
    int ti, tj;
    decode_pair(blockIdx.x, ti, tj);
    bool diag = (ti == tj);
    int i0 = ti * 128, j0 = tj * 128;
    size_t aBaseG = (size_t)i0 * DIM;                      // element offset of A tile
    size_t bBaseG = (size_t)j0 * DIM;

    // issue stage-0 loads for the first tile
    {
#pragma unroll
        for (int v = 0; v < 4; v++) {
            cp16(sb + dsw[v], goff[v] + aBaseG);
            if (!diag) cp16(sb + NSTAGE * STAGE_BYTES + dsw[v], goff[v] + bBaseG);
        }
        asm volatile("cp.async.commit_group;\n");
    }

    while (true) {
        const uint32_t sB_read = diag ? sb : (sb + NSTAGE * STAGE_BYTES);

        // f16 accumulators: 2 regs (4 halves) per 16x8 tile
        uint32_t acc[4][4][2];
#pragma unroll
        for (int mt = 0; mt < 4; mt++)
#pragma unroll
            for (int nt = 0; nt < 4; nt++) { acc[mt][nt][0] = 0u; acc[mt][nt][1] = 0u; }

        // ---- mainloop: 2-stage double buffer, prefetch distance 1 ----
        for (int kk = 0; kk < KITER; kk++) {
            asm volatile("cp.async.wait_group 0;\n");
            __syncthreads();

            if (kk + 1 < KITER) {
                const int s = (kk + 1) & 1;
                const int k0 = (kk + 1) * BK;
                const uint32_t aB = sb + s * STAGE_BYTES;
                const uint32_t bB = sb + NSTAGE * STAGE_BYTES + s * STAGE_BYTES;
#pragma unroll
                for (int v = 0; v < 4; v++) {
                    cp16(aB + dsw[v], goff[v] + aBaseG + k0);
                    if (!diag) cp16(bB + dsw[v], goff[v] + bBaseG + k0);
                }
                asm volatile("cp.async.commit_group;\n");
            }

            const int s = kk & 1;
            const uint32_t aT = sb + s * STAGE_BYTES;
            const uint32_t bT = sB_read + s * STAGE_BYTES;

#pragma unroll
            for (int ks = 0; ks < 4; ks++) {
                const uint32_t kb = (uint32_t)(ks * 32);
                uint32_t af[4][4], bf[4][2];
#pragma unroll
                for (int mt = 0; mt < 4; mt++) {
                    const uint32_t addr = aT + aRow + (uint32_t)(mt * 2048)
                                        + ((kb + aKh) ^ aXor);
                    ldsm4(af[mt][0], af[mt][1], af[mt][2], af[mt][3], addr);
                }
#pragma unroll
                for (int np = 0; np < 2; np++) {
                    const uint32_t addr = bT + bRow + (uint32_t)(np * 2048)
                                        + ((kb + bKh) ^ bXor);
                    ldsm4(bf[np * 2][0], bf[np * 2][1], bf[np * 2 + 1][0], bf[np * 2 + 1][1], addr);
                }
#pragma unroll
                for (int mt = 0; mt < 4; mt++)
#pragma unroll
                    for (int nt = 0; nt < 4; nt++) {
                        asm volatile(
                            "mma.sync.aligned.m16n8k16.row.col.f16.f16.f16.f16 "
                            "{%0,%1}, {%2,%3,%4,%5}, {%6,%7}, {%0,%1};\n"
                            : "+r"(acc[mt][nt][0]), "+r"(acc[mt][nt][1])
                            : "r"(af[mt][0]), "r"(af[mt][1]),
                              "r"(af[mt][2]), "r"(af[mt][3]),
                              "r"(bf[nt][0]), "r"(bf[nt][1]));
                    }
            }
        }

        // ---- steal next tile, issue its stage-0 loads (overlap epilogue) ----
        __syncthreads();                 // all warps done with mainloop reads
        if (tid == 0) s_pair = (int)atomicAdd(&g_work, 1u);
        __syncthreads();
        const int t_next = s_pair;
        int nti = 0, ntj = 0;
        bool ndiag = false;
        size_t naBaseG = 0, nbBaseG = 0;
        if (t_next < NPAIR) {
            decode_pair(t_next, nti, ntj);
            ndiag = (nti == ntj);
            naBaseG = (size_t)(nti * 128) * DIM;
            nbBaseG = (size_t)(ntj * 128) * DIM;
            // stage 0 free: its last reader was k-iter 30, barrier above passed
#pragma unroll
            for (int v = 0; v < 4; v++) {
                cp16(sb + dsw[v], goff[v] + naBaseG);
                if (!ndiag) cp16(sb + NSTAGE * STAGE_BYTES + dsw[v], goff[v] + nbBaseG);
            }
            asm volatile("cp.async.commit_group;\n");
        }

        // ---- epilogue for current tile ----
        // row-argmax (rows i0.. over cols j0..)
#pragma unroll
        for (int mt = 0; mt < 4; mt++) {
#pragma unroll
            for (int h = 0; h < 2; h++) {
                const int mrow = wr * 64 + mt * 16 + qr + 8 * h;
                unsigned long long b = 0ULL;
                if (diag) {
                    const int igrp = (i0 + mrow) >> 2;
#pragma unroll
                    for (int nt = 0; nt < 4; nt++) {
                        const float2 p = __half22float2(
                            *reinterpret_cast<__half2*>(&acc[mt][nt][h]));
                        const int jg = j0 + wc * 32 + nt * 8 + qc;
                        if ((jg >> 2) != igrp) {
                            b = umax64(b, packmax(p.x, jg));
                            b = umax64(b, packmax(p.y, jg + 1));
                        }
                    }
                } else {
#pragma unroll
                    for (int nt = 0; nt < 4; nt++) {
                        const float2 p = __half22float2(
                            *reinterpret_cast<__half2*>(&acc[mt][nt][h]));
                        const int jg = j0 + wc * 32 + nt * 8 + qc;
                        b = umax64(b, packmax(p.x, jg));
                        b = umax64(b, packmax(p.y, jg + 1));
                    }
                }
                b = umax64(b, __shfl_xor_sync(0xFFFFFFFFu, b, 1));
                b = umax64(b, __shfl_xor_sync(0xFFFFFFFFu, b, 2));
                if ((lane & 3) == 0) atomicMax(&rowbest_s[mrow], b);
            }
        }

        // col-argmax (cols j0.. over rows i0..); sim[j][i] by symmetry
        if (!diag) {
#pragma unroll
            for (int nt = 0; nt < 4; nt++) {
#pragma unroll
                for (int c = 0; c < 2; c++) {
                    unsigned long long b = 0ULL;
#pragma unroll
                    for (int mt = 0; mt < 4; mt++)
#pragma unroll
                        for (int h = 0; h < 2; h++) {
                            const __half2 hv = *reinterpret_cast<__half2*>(&acc[mt][nt][h]);
                            const float v = (c == 0) ? __low2float(hv) : __high2float(hv);
                            const int ig = i0 + wr * 64 + mt * 16 + qr + 8 * h;
                            b = umax64(b, packmax(v, ig));
                        }
                    b = umax64(b, __shfl_xor_sync(0xFFFFFFFFu, b, 4));
                    b = umax64(b, __shfl_xor_sync(0xFFFFFFFFu, b, 8));
                    b = umax64(b, __shfl_xor_sync(0xFFFFFFFFu, b, 16));
                    if (lane < 4)
                        atomicMax(&colbest_s[wc * 32 + nt * 8 + qc + c], b);
                }
            }
        }
        __syncthreads();
        if (tid < 128) {
            atomicMax(&g_best[i0 + tid], rowbest_s[tid]);
            if (!diag) atomicMax(&g_best[j0 + tid], colbest_s[tid]);
            rowbest_s[tid] = 0ULL;
            colbest_s[tid] = 0ULL;
        }
        // re-zero is ordered before next epilogue by mainloop's per-iter barriers

        if (t_next >= NPAIR) break;
        ti = nti; tj = ntj; diag = ndiag;
        i0 = ti * 128; j0 = tj * 128;
        aBaseG = naBaseG; bBaseG = nbBaseG;
    }
}

// ---------------------------------------------------------------------------
// Kernel 3: d_an gather + weighted ratio sum (float4 vectorized, exact fp32)
// ---------------------------------------------------------------------------
__global__ void finalize_kernel(const float* __restrict__ x, float* out) {
    const int i = blockIdx.x;
    const unsigned jg = ~(unsigned)(g_best[i] & 0xFFFFFFFFULL);
    const float4* xi = reinterpret_cast<const float4*>(x + (size_t)i * DIM);
    const float4* xj = reinterpret_cast<const float4*>(x + (size_t)jg * DIM);

    float s = 0.0f;
    for (int d = threadIdx.x; d < DIM / 4; d += 256) {
        const float4 a = xi[d], b = xj[d];
        s += fabsf(a.x - b.x) + fabsf(a.y - b.y) + fabsf(a.z - b.z) + fabsf(a.w - b.w);
    }
#pragma unroll
    for (int o = 16; o > 0; o >>= 1)
        s += __shfl_xor_sync(0xFFFFFFFFu, s, o);

    __shared__ float sw[8];
    if ((threadIdx.x & 31) == 0) sw[threadIdx.x >> 5] = s;
    __syncthreads();
    if (threadIdx.x == 0) {
        float tot = 0.0f;
#pragma unroll
        for (int w = 0; w < 8; w++) tot += sw[w];
        const float dan = tot / (float)DIM;
        atomicAdd(out, 0.125f * g_dap[i] / (dan + 1e-7f));
    }
}

// ---------------------------------------------------------------------------
extern "C" void kernel_launch(void* const* d_in, const int* in_sizes, int n_in,
                              void* d_out, int out_size) {
    const float* x = (const float*)d_in[0];
    float* out = (float*)d_out;

    static bool attr_set = false;
    if (!attr_set) {
        cudaFuncSetAttribute(simgemm_kernel,
                             cudaFuncAttributeMaxDynamicSharedMemorySize, SMEM_BYTES);
        attr_set = true;
    }

    prep_kernel<<<NROWS / CS, 512>>>(x, out);
    simgemm_kernel<<<NCTA_PERSIST, 256, SMEM_BYTES>>>();
    finalize_kernel<<<NROWS, 256>>>(x, out);
}

// round 16
// speedup vs baseline: 1.0343x; 1.0343x over previous
#include <cuda_runtime.h>
#include <cuda_fp16.h>
#include <cstdint>

// ---------------------------------------------------------------------------
// Problem constants
// ---------------------------------------------------------------------------
#define NROWS 8192
#define DIM   2048
#define CS    8
#define NT    (NROWS / 128)            // 64 row-tiles of 128
#define NPAIR (NT * (NT + 1) / 2)      // 2080 symmetric tile pairs
#define BK    64
#define KITER (DIM / BK)               // 32
#define NSTAGE 2
#define STAGE_BYTES 16384              // 128 rows x 128 bytes (64 f16)
#define SMEM_BYTES (NSTAGE * STAGE_BYTES * 2)   // 65536: A stages then B stages
#define NCTA_PERSIST 444               // 148 SMs x 3 CTAs

// Scratch (device globals; no allocations allowed)
__device__ __half g_xh[(size_t)NROWS * DIM];          // f16 copy of x (32 MB)
__device__ float g_dap[NROWS];
__device__ unsigned long long g_best[NROWS];          // packed (mono(f32)<<32) | ~idx
__device__ unsigned g_work;                           // persistent work counter

// ---------------------------------------------------------------------------
// helpers
// ---------------------------------------------------------------------------
__device__ __forceinline__ void cp16(uint32_t dst, const void* src) {
    asm volatile("cp.async.cg.shared.global [%0], [%1], 16;\n" :: "r"(dst), "l"(src));
}
__device__ __forceinline__ void ldsm4(uint32_t& r0, uint32_t& r1, uint32_t& r2, uint32_t& r3,
                                      uint32_t a) {
    asm volatile("ldmatrix.sync.aligned.m8n8.x4.shared.b16 {%0,%1,%2,%3}, [%4];"
                 : "=r"(r0), "=r"(r1), "=r"(r2), "=r"(r3) : "r"(a));
}
__device__ __forceinline__ uint32_t smem_u32(const void* p) {
    uint32_t a;
    asm("{ .reg .u64 t; cvta.to.shared.u64 t, %1; cvt.u32.u64 %0, t; }" : "=r"(a) : "l"(p));
    return a;
}
__device__ __forceinline__ unsigned long long packmax(float v, int idx) {
    unsigned fb = __float_as_uint(v);
    unsigned mono = (fb & 0x80000000u) ? ~fb : (fb | 0x80000000u);
    return ((unsigned long long)mono << 32) | (unsigned)(~idx);
}
__device__ __forceinline__ unsigned long long umax64(unsigned long long a, unsigned long long b) {
    return a > b ? a : b;
}
// decode linear pair index -> (ti, tj), ti <= tj
__device__ __forceinline__ void decode_pair(int t, int& ti, int& tj) {
    int len = NT;
    ti = 0;
    while (t >= len) { t -= len; len--; ti++; }
    tj = ti + t;
}

// ---------------------------------------------------------------------------
// Kernel 1: chunk centers -> d_ap, fp32 -> f16 conversion, resets
// 512 threads, loop-free (DIM/4 == 512)
// ---------------------------------------------------------------------------
__global__ __launch_bounds__(512) void prep_kernel(const float* __restrict__ x, float* out) {
    const int r0 = blockIdx.x * CS;
    const int d  = threadIdx.x;                    // 0..511 == DIM/4 columns

    if (threadIdx.x < CS) g_best[r0 + threadIdx.x] = 0ULL;
    if (blockIdx.x == 0 && threadIdx.x == 0) { out[0] = 0.0f; g_work = NCTA_PERSIST; }

    float acc[CS];
    float4 v[CS];
    float4 s = make_float4(0.f, 0.f, 0.f, 0.f);
#pragma unroll
    for (int k = 0; k < CS; k++) {
        v[k] = reinterpret_cast<const float4*>(x + (size_t)(r0 + k) * DIM)[d];
        s.x += v[k].x; s.y += v[k].y; s.z += v[k].z; s.w += v[k].w;
    }
    const float4 c = make_float4(s.x * 0.125f, s.y * 0.125f, s.z * 0.125f, s.w * 0.125f);
#pragma unroll
    for (int k = 0; k < CS; k++) {
        acc[k] = fabsf(v[k].x - c.x) + fabsf(v[k].y - c.y)
               + fabsf(v[k].z - c.z) + fabsf(v[k].w - c.w);
        __half2 lo = __floats2half2_rn(v[k].x, v[k].y);
        __half2 hi = __floats2half2_rn(v[k].z, v[k].w);
        uint2 u;
        u.x = *reinterpret_cast<unsigned*>(&lo);
        u.y = *reinterpret_cast<unsigned*>(&hi);
        *reinterpret_cast<uint2*>(&g_xh[(size_t)(r0 + k) * DIM + d * 4]) = u;
    }

    __shared__ float sred[CS];
    if (threadIdx.x < CS) sred[threadIdx.x] = 0.0f;
    __syncthreads();
#pragma unroll
    for (int k = 0; k < CS; k++)
#pragma unroll
        for (int o = 16; o > 0; o >>= 1)
            acc[k] += __shfl_xor_sync(0xFFFFFFFFu, acc[k], o);
    if ((threadIdx.x & 31) == 0)
#pragma unroll
        for (int k = 0; k < CS; k++) atomicAdd(&sred[k], acc[k]);
    __syncthreads();
    if (threadIdx.x < CS)
        g_dap[r0 + threadIdx.x] = 0.5f * sred[threadIdx.x] / (float)DIM;
}

// ---------------------------------------------------------------------------
// Kernel 2: PERSISTENT symmetric sim-GEMM (f16 in, f16 acc) — register-lean.
// Mainloop identical to the static R12 kernel; persistence state kept minimal
// (two pointers + shared s_pair), all cp.async addressing recomputed inline.
// grid = NCTA_PERSIST, block = 256 (8 warps: 2(M) x 4(N), each 64x32)
// ---------------------------------------------------------------------------
__global__ __launch_bounds__(256, 3) void simgemm_kernel() {
    extern __shared__ char smem[];
    __shared__ unsigned long long rowbest_s[128];
    __shared__ unsigned long long colbest_s[128];
    __shared__ int s_pair;

    const uint32_t sb = smem_u32(smem);
    const int tid  = threadIdx.x;
    const int lane = tid & 31;
    const int warp = tid >> 5;
    const int wr   = warp >> 2;        // 0..1 -> M offset wr*64
    const int wc   = warp & 3;         // 0..3 -> N offset wc*32
    const int qr   = lane >> 2;        // 0..7
    const int qc   = (lane & 3) * 2;   // 0,2,4,6

    if (tid < 128) { rowbest_s[tid] = 0ULL; colbest_s[tid] = 0ULL; }

    // per-lane ldmatrix addressing constants
    const int am    = wr * 64 + (lane & 15);               // A row for this lane
    const uint32_t aRow = (uint32_t)am * 128;
    const uint32_t aXor = (uint32_t)((am & 7) << 4);
    const uint32_t aKh  = (uint32_t)((lane >> 4) * 16);    // k-half byte offset
    const int bn    = wc * 32 + (lane & 7) + ((lane >> 4) << 3);  // B (n) row
    const uint32_t bRow = (uint32_t)bn * 128;
    const uint32_t bXor = (uint32_t)((bn & 7) << 4);
    const uint32_t bKh  = (uint32_t)(((lane >> 3) & 1) * 16);

    // current tile state (minimal: mirrors R12 exactly)
    int ti, tj;
    decode_pair(blockIdx.x, ti, tj);
    bool diag = (ti == tj);
    int i0 = ti * 128, j0 = tj * 128;
    const __half* gA = g_xh + (size_t)i0 * DIM;
    const __half* gB = g_xh + (size_t)j0 * DIM;

    // stage-0 loads for the first tile (addressing computed inline, as in R12)
    {
#pragma unroll
        for (int v = 0; v < 4; v++) {
            const int idx = tid + v * 256;
            const int row = idx >> 3;
            const int c8  = (idx & 7) * 8;
            const uint32_t off = row * 128 + c8 * 2;
            const uint32_t sw  = off ^ ((off >> 3) & 0x70);
            cp16(sb + sw, gA + (size_t)row * DIM + c8);
            if (!diag) cp16(sb + NSTAGE * STAGE_BYTES + sw, gB + (size_t)row * DIM + c8);
        }
        asm volatile("cp.async.commit_group;\n");
    }

    while (true) {
        const uint32_t sB_read = diag ? sb : (sb + NSTAGE * STAGE_BYTES);

        // f16 accumulators: 2 regs (4 halves) per 16x8 tile
        uint32_t acc[4][4][2];
#pragma unroll
        for (int mt = 0; mt < 4; mt++)
#pragma unroll
            for (int nt = 0; nt < 4; nt++) { acc[mt][nt][0] = 0u; acc[mt][nt][1] = 0u; }

        // ---- mainloop: identical to R12 ----
        for (int kk = 0; kk < KITER; kk++) {
            asm volatile("cp.async.wait_group 0;\n");
            __syncthreads();

            if (kk + 1 < KITER) {
                const int s = (kk + 1) & 1;
                const int k0 = (kk + 1) * BK;
                const uint32_t aB = sb + s * STAGE_BYTES;
                const uint32_t bB = sb + NSTAGE * STAGE_BYTES + s * STAGE_BYTES;
#pragma unroll
                for (int v = 0; v < 4; v++) {
                    const int idx = tid + v * 256;
                    const int row = idx >> 3;
                    const int c8  = (idx & 7) * 8;
                    const uint32_t off = row * 128 + c8 * 2;
                    const uint32_t sw  = off ^ ((off >> 3) & 0x70);
                    cp16(aB + sw, gA + (size_t)row * DIM + k0 + c8);
                    if (!diag) cp16(bB + sw, gB + (size_t)row * DIM + k0 + c8);
                }
                asm volatile("cp.async.commit_group;\n");
            }

            const int s = kk & 1;
            const uint32_t aT = sb + s * STAGE_BYTES;
            const uint32_t bT = sB_read + s * STAGE_BYTES;

#pragma unroll
            for (int ks = 0; ks < 4; ks++) {
                const uint32_t kb = (uint32_t)(ks * 32);
                uint32_t af[4][4], bf[4][2];
#pragma unroll
                for (int mt = 0; mt < 4; mt++) {
                    const uint32_t addr = aT + aRow + (uint32_t)(mt * 2048)
                                        + ((kb + aKh) ^ aXor);
                    ldsm4(af[mt][0], af[mt][1], af[mt][2], af[mt][3], addr);
                }
#pragma unroll
                for (int np = 0; np < 2; np++) {
                    const uint32_t addr = bT + bRow + (uint32_t)(np * 2048)
                                        + ((kb + bKh) ^ bXor);
                    ldsm4(bf[np * 2][0], bf[np * 2][1], bf[np * 2 + 1][0], bf[np * 2 + 1][1], addr);
                }
#pragma unroll
                for (int mt = 0; mt < 4; mt++)
#pragma unroll
                    for (int nt = 0; nt < 4; nt++) {
                        asm volatile(
                            "mma.sync.aligned.m16n8k16.row.col.f16.f16.f16.f16 "
                            "{%0,%1}, {%2,%3,%4,%5}, {%6,%7}, {%0,%1};\n"
                            : "+r"(acc[mt][nt][0]), "+r"(acc[mt][nt][1])
                            : "r"(af[mt][0]), "r"(af[mt][1]),
                              "r"(af[mt][2]), "r"(af[mt][3]),
                              "r"(bf[nt][0]), "r"(bf[nt][1]));
                    }
            }
        }

        // ---- steal next tile; issue its stage-0 loads (overlaps epilogue) ----
        __syncthreads();                 // all warps done with stage reads
        if (tid == 0) s_pair = (int)atomicAdd(&g_work, 1u);
        __syncthreads();
        const int t_next = s_pair;
        const __half* ngA = gA;
        const __half* ngB = gB;
        bool ndiag = diag;
        if (t_next < NPAIR) {
            int nti, ntj;
            decode_pair(t_next, nti, ntj);     // all threads decode (cheap ALU)
            ndiag = (nti == ntj);
            ngA = g_xh + (size_t)(nti * 128) * DIM;
            ngB = g_xh + (size_t)(ntj * 128) * DIM;
#pragma unroll
            for (int v = 0; v < 4; v++) {
                const int idx = tid + v * 256;
                const int row = idx >> 3;
                const int c8  = (idx & 7) * 8;
                const uint32_t off = row * 128 + c8 * 2;
                const uint32_t sw  = off ^ ((off >> 3) & 0x70);
                cp16(sb + sw, ngA + (size_t)row * DIM + c8);
                if (!ndiag) cp16(sb + NSTAGE * STAGE_BYTES + sw, ngB + (size_t)row * DIM + c8);
            }
            asm volatile("cp.async.commit_group;\n");
        }

        // ---- epilogue for current tile ----
#pragma unroll
        for (int mt = 0; mt < 4; mt++) {
#pragma unroll
            for (int h = 0; h < 2; h++) {
                const int mrow = wr * 64 + mt * 16 + qr + 8 * h;
                unsigned long long b = 0ULL;
                if (diag) {
                    const int igrp = (i0 + mrow) >> 2;
#pragma unroll
                    for (int nt = 0; nt < 4; nt++) {
                        const float2 p = __half22float2(
                            *reinterpret_cast<__half2*>(&acc[mt][nt][h]));
                        const int jg = j0 + wc * 32 + nt * 8 + qc;
                        if ((jg >> 2) != igrp) {
                            b = umax64(b, packmax(p.x, jg));
                            b = umax64(b, packmax(p.y, jg + 1));
                        }
                    }
                } else {
#pragma unroll
                    for (int nt = 0; nt < 4; nt++) {
                        const float2 p = __half22float2(
                            *reinterpret_cast<__half2*>(&acc[mt][nt][h]));
                        const int jg = j0 + wc * 32 + nt * 8 + qc;
                        b = umax64(b, packmax(p.x, jg));
                        b = umax64(b, packmax(p.y, jg + 1));
                    }
                }
                b = umax64(b, __shfl_xor_sync(0xFFFFFFFFu, b, 1));
                b = umax64(b, __shfl_xor_sync(0xFFFFFFFFu, b, 2));
                if ((lane & 3) == 0) atomicMax(&rowbest_s[mrow], b);
            }
        }

        if (!diag) {
#pragma unroll
            for (int nt = 0; nt < 4; nt++) {
#pragma unroll
                for (int c = 0; c < 2; c++) {
                    unsigned long long b = 0ULL;
#pragma unroll
                    for (int mt = 0; mt < 4; mt++)
#pragma unroll
                        for (int h = 0; h < 2; h++) {
                            const __half2 hv = *reinterpret_cast<__half2*>(&acc[mt][nt][h]);
                            const float v = (c == 0) ? __low2float(hv) : __high2float(hv);
                            const int ig = i0 + wr * 64 + mt * 16 + qr + 8 * h;
                            b = umax64(b, packmax(v, ig));
                        }
                    b = umax64(b, __shfl_xor_sync(0xFFFFFFFFu, b, 4));
                    b = umax64(b, __shfl_xor_sync(0xFFFFFFFFu, b, 8));
                    b = umax64(b, __shfl_xor_sync(0xFFFFFFFFu, b, 16));
                    if (lane < 4)
                        atomicMax(&colbest_s[wc * 32 + nt * 8 + qc + c], b);
                }
            }
        }
        __syncthreads();
        if (tid < 128) {
            atomicMax(&g_best[i0 + tid], rowbest_s[tid]);
            if (!diag) atomicMax(&g_best[j0 + tid], colbest_s[tid]);
            rowbest_s[tid] = 0ULL;       // re-read only after next mainloop's barriers
            colbest_s[tid] = 0ULL;
        }

        if (t_next >= NPAIR) break;
        gA = ngA; gB = ngB; diag = ndiag;
        i0 = (t_next < NPAIR) ? 0 : i0;  // recomputed below
        // recompute i0/j0 from pointers (avoid carrying nti/ntj live regs)
        i0 = (int)((size_t)(gA - g_xh) / DIM);
        j0 = (int)((size_t)(gB - g_xh) / DIM);
    }
}

// ---------------------------------------------------------------------------
// Kernel 3: d_an gather + weighted ratio sum (float4 vectorized, exact fp32)
// ---------------------------------------------------------------------------
__global__ void finalize_kernel(const float* __restrict__ x, float* out) {
    const int i = blockIdx.x;
    const unsigned jg = ~(unsigned)(g_best[i] & 0xFFFFFFFFULL);
    const float4* xi = reinterpret_cast<const float4*>(x + (size_t)i * DIM);
    const float4* xj = reinterpret_cast<const float4*>(x + (size_t)jg * DIM);

    float s = 0.0f;
    for (int d = threadIdx.x; d < DIM / 4; d += 256) {
        const float4 a = xi[d], b = xj[d];
        s += fabsf(a.x - b.x) + fabsf(a.y - b.y) + fabsf(a.z - b.z) + fabsf(a.w - b.w);
    }
#pragma unroll
    for (int o = 16; o > 0; o >>= 1)
        s += __shfl_xor_sync(0xFFFFFFFFu, s, o);

    __shared__ float sw[8];
    if ((threadIdx.x & 31) == 0) sw[threadIdx.x >> 5] = s;
    __syncthreads();
    if (threadIdx.x == 0) {
        float tot = 0.0f;
#pragma unroll
        for (int w = 0; w < 8; w++) tot += sw[w];
        const float dan = tot / (float)DIM;
        atomicAdd(out, 0.125f * g_dap[i] / (dan + 1e-7f));
    }
}

// ---------------------------------------------------------------------------
extern "C" void kernel_launch(void* const* d_in, const int* in_sizes, int n_in,
                              void* d_out, int out_size) {
    const float* x = (const float*)d_in[0];
    float* out = (float*)d_out;

    static bool attr_set = false;
    if (!attr_set) {
        cudaFuncSetAttribute(simgemm_kernel,
                             cudaFuncAttributeMaxDynamicSharedMemorySize, SMEM_BYTES);
        attr_set = true;
    }

    prep_kernel<<<NROWS / CS, 512>>>(x, out);
    simgemm_kernel<<<NCTA_PERSIST, 256, SMEM_BYTES>>>();
    finalize_kernel<<<NROWS, 256>>>(x, out);
}

// round 17
// speedup vs baseline: 1.3097x; 1.2663x over previous
#include <cuda_runtime.h>
#include <cuda_fp16.h>
#include <cstdint>

// ---------------------------------------------------------------------------
// Problem constants
// ---------------------------------------------------------------------------
#define NROWS 8192
#define DIM   2048
#define CS    8
#define NT    (NROWS / 128)            // 64 row-tiles of 128
#define NPAIR (NT * (NT + 1) / 2)      // 2080 symmetric tile pairs
#define BK    64
#define KITER (DIM / BK)               // 32
#define NSTAGE 2
#define STAGE_BYTES 16384              // 128 rows x 128 bytes (64 f16)
#define SMEM_BYTES (NSTAGE * STAGE_BYTES * 2)   // 65536: A stages then B stages

// Scratch (device globals; no allocations allowed)
__device__ __half g_xh[(size_t)NROWS * DIM];          // f16 copy of x (32 MB)
__device__ float g_dap[NROWS];
__device__ unsigned long long g_best[NROWS];          // packed (mono(f32)<<32) | ~idx

// ---------------------------------------------------------------------------
// helpers
// ---------------------------------------------------------------------------
__device__ __forceinline__ void cp16(uint32_t dst, const void* src) {
    asm volatile("cp.async.cg.shared.global [%0], [%1], 16;\n" :: "r"(dst), "l"(src));
}
__device__ __forceinline__ void ldsm4(uint32_t& r0, uint32_t& r1, uint32_t& r2, uint32_t& r3,
                                      uint32_t a) {
    asm volatile("ldmatrix.sync.aligned.m8n8.x4.shared.b16 {%0,%1,%2,%3}, [%4];"
                 : "=r"(r0), "=r"(r1), "=r"(r2), "=r"(r3) : "r"(a));
}
__device__ __forceinline__ uint32_t smem_u32(const void* p) {
    uint32_t a;
    asm("{ .reg .u64 t; cvta.to.shared.u64 t, %1; cvt.u32.u64 %0, t; }" : "=r"(a) : "l"(p));
    return a;
}
__device__ __forceinline__ unsigned long long packmax(float v, int idx) {
    unsigned fb = __float_as_uint(v);
    unsigned mono = (fb & 0x80000000u) ? ~fb : (fb | 0x80000000u);
    return ((unsigned long long)mono << 32) | (unsigned)(~idx);
}
__device__ __forceinline__ unsigned long long umax64(unsigned long long a, unsigned long long b) {
    return a > b ? a : b;
}

// ---------------------------------------------------------------------------
// Kernel 1: chunk centers -> d_ap, fp32 -> f16 conversion, resets
// 512 threads, loop-free (DIM/4 == 512)
// ---------------------------------------------------------------------------
__global__ __launch_bounds__(512) void prep_kernel(const float* __restrict__ x, float* out) {
    const int r0 = blockIdx.x * CS;
    const int d  = threadIdx.x;                    // 0..511 == DIM/4 columns

    if (threadIdx.x < CS) g_best[r0 + threadIdx.x] = 0ULL;
    if (blockIdx.x == 0 && threadIdx.x == 0) out[0] = 0.0f;

    float acc[CS];
    float4 v[CS];
    float4 s = make_float4(0.f, 0.f, 0.f, 0.f);
#pragma unroll
    for (int k = 0; k < CS; k++) {
        v[k] = reinterpret_cast<const float4*>(x + (size_t)(r0 + k) * DIM)[d];
        s.x += v[k].x; s.y += v[k].y; s.z += v[k].z; s.w += v[k].w;
    }
    const float4 c = make_float4(s.x * 0.125f, s.y * 0.125f, s.z * 0.125f, s.w * 0.125f);
#pragma unroll
    for (int k = 0; k < CS; k++) {
        acc[k] = fabsf(v[k].x - c.x) + fabsf(v[k].y - c.y)
               + fabsf(v[k].z - c.z) + fabsf(v[k].w - c.w);
        __half2 lo = __floats2half2_rn(v[k].x, v[k].y);
        __half2 hi = __floats2half2_rn(v[k].z, v[k].w);
        uint2 u;
        u.x = *reinterpret_cast<unsigned*>(&lo);
        u.y = *reinterpret_cast<unsigned*>(&hi);
        *reinterpret_cast<uint2*>(&g_xh[(size_t)(r0 + k) * DIM + d * 4]) = u;
    }

    __shared__ float sred[CS];
    if (threadIdx.x < CS) sred[threadIdx.x] = 0.0f;
    __syncthreads();
#pragma unroll
    for (int k = 0; k < CS; k++)
#pragma unroll
        for (int o = 16; o > 0; o >>= 1)
            acc[k] += __shfl_xor_sync(0xFFFFFFFFu, acc[k], o);
    if ((threadIdx.x & 31) == 0)
#pragma unroll
        for (int k = 0; k < CS; k++) atomicAdd(&sred[k], acc[k]);
    __syncthreads();
    if (threadIdx.x < CS)
        g_dap[r0 + threadIdx.x] = 0.5f * sred[threadIdx.x] / (float)DIM;
}

// ---------------------------------------------------------------------------
// Kernel 2: symmetric sim-GEMM (mma.sync f16 in, f16 acc), 128x128 tile pairs
// ti<=tj, 2-stage cp.async double buffer (k-loop unrolled x2 so stage
// addressing is compile-time), SW128 swizzle + ldmatrix, fused row+col argmax.
// STATIC grid = NPAIR (HW CLC work-steals waves >= 2; software persistence
// measured slower twice). block = 256 (8 warps: 2(M) x 4(N), each 64x32)
// ---------------------------------------------------------------------------
struct TileCtx {
    const __half* gA;
    const __half* gB;
    bool diag;
};

__device__ __forceinline__ void prefetch_stage(
    uint32_t sb, int stage, int k0, int tid, const TileCtx& tc) {
    const uint32_t aB = sb + stage * STAGE_BYTES;
    if (tc.diag) {
#pragma unroll
        for (int v = 0; v < 4; v++) {
            const int idx = tid + v * 256;
            const int row = idx >> 3;
            const int c8  = (idx & 7) * 8;
            const uint32_t off = row * 128 + c8 * 2;
            const uint32_t sw  = off ^ ((off >> 3) & 0x70);
            cp16(aB + sw, tc.gA + (size_t)row * DIM + k0 + c8);
        }
    } else {
        const uint32_t bB = aB + NSTAGE * STAGE_BYTES;
#pragma unroll
        for (int v = 0; v < 4; v++) {
            const int idx = tid + v * 256;
            const int row = idx >> 3;
            const int c8  = (idx & 7) * 8;
            const uint32_t off = row * 128 + c8 * 2;
            const uint32_t sw  = off ^ ((off >> 3) & 0x70);
            cp16(aB + sw, tc.gA + (size_t)row * DIM + k0 + c8);
            cp16(bB + sw, tc.gB + (size_t)row * DIM + k0 + c8);
        }
    }
    asm volatile("cp.async.commit_group;\n");
}

__global__ __launch_bounds__(256, 3) void simgemm_kernel() {
    extern __shared__ char smem[];
    __shared__ unsigned long long rowbest_s[128];
    __shared__ unsigned long long colbest_s[128];

    const uint32_t sb = smem_u32(smem);
    const int tid  = threadIdx.x;
    const int lane = tid & 31;
    const int warp = tid >> 5;
    const int wr   = warp >> 2;        // 0..1 -> M offset wr*64
    const int wc   = warp & 3;         // 0..3 -> N offset wc*32
    const int qr   = lane >> 2;        // 0..7
    const int qc   = (lane & 3) * 2;   // 0,2,4,6

    // pair decode: blockIdx.x -> (ti, tj), ti <= tj
    int t = blockIdx.x, ti = 0, len = NT;
    while (t >= len) { t -= len; len--; ti++; }
    const int tj = ti + t;
    const bool diag = (ti == tj);
    const int i0 = ti * 128, j0 = tj * 128;

    if (tid < 128) { rowbest_s[tid] = 0ULL; colbest_s[tid] = 0ULL; }

    TileCtx tc;
    tc.gA = g_xh + (size_t)i0 * DIM;
    tc.gB = g_xh + (size_t)j0 * DIM;
    tc.diag = diag;
    const uint32_t sB_read = diag ? sb : (sb + NSTAGE * STAGE_BYTES);

    // ---- prologue: fill stage 0 ----
    prefetch_stage(sb, 0, 0, tid, tc);

    // f16 accumulators: 2 regs (4 halves) per 16x8 tile
    uint32_t acc[4][4][2];
#pragma unroll
    for (int mt = 0; mt < 4; mt++)
#pragma unroll
        for (int nt = 0; nt < 4; nt++) { acc[mt][nt][0] = 0u; acc[mt][nt][1] = 0u; }

    // per-lane ldmatrix addressing constants
    const int am    = wr * 64 + (lane & 15);               // A row for this lane
    const uint32_t aRow = (uint32_t)am * 128;
    const uint32_t aXor = (uint32_t)((am & 7) << 4);
    const uint32_t aKh  = (uint32_t)((lane >> 4) * 16);    // k-half byte offset
    const int bn    = wc * 32 + (lane & 7) + ((lane >> 4) << 3);  // B (n) row
    const uint32_t bRow = (uint32_t)bn * 128;
    const uint32_t bXor = (uint32_t)((bn & 7) << 4);
    const uint32_t bKh  = (uint32_t)(((lane >> 3) & 1) * 16);

    // one k-iteration of compute on stage `stg` (compile-time constant)
    auto compute_stage = [&](const int stg) {
        const uint32_t aT = sb + stg * STAGE_BYTES;
        const uint32_t bT = sB_read + stg * STAGE_BYTES;
#pragma unroll
        for (int ks = 0; ks < 4; ks++) {
            const uint32_t kb = (uint32_t)(ks * 32);
            uint32_t af[4][4], bf[4][2];
#pragma unroll
            for (int mt = 0; mt < 4; mt++) {
                const uint32_t addr = aT + aRow + (uint32_t)(mt * 2048)
                                    + ((kb + aKh) ^ aXor);
                ldsm4(af[mt][0], af[mt][1], af[mt][2], af[mt][3], addr);
            }
#pragma unroll
            for (int np = 0; np < 2; np++) {
                const uint32_t addr = bT + bRow + (uint32_t)(np * 2048)
                                    + ((kb + bKh) ^ bXor);
                ldsm4(bf[np * 2][0], bf[np * 2][1], bf[np * 2 + 1][0], bf[np * 2 + 1][1], addr);
            }
#pragma unroll
            for (int mt = 0; mt < 4; mt++)
#pragma unroll
                for (int nt = 0; nt < 4; nt++) {
                    asm volatile(
                        "mma.sync.aligned.m16n8k16.row.col.f16.f16.f16.f16 "
                        "{%0,%1}, {%2,%3,%4,%5}, {%6,%7}, {%0,%1};\n"
                        : "+r"(acc[mt][nt][0]), "+r"(acc[mt][nt][1])
                        : "r"(af[mt][0]), "r"(af[mt][1]),
                          "r"(af[mt][2]), "r"(af[mt][3]),
                          "r"(bf[nt][0]), "r"(bf[nt][1]));
                }
        }
    };

    // ---- mainloop: unrolled x2, stage indices compile-time ----
#pragma unroll 1
    for (int kk = 0; kk < KITER; kk += 2) {
        // even iter: compute stage 0, prefetch kk+1 -> stage 1
        asm volatile("cp.async.wait_group 0;\n");
        __syncthreads();
        prefetch_stage(sb, 1, (kk + 1) * BK, tid, tc);
        compute_stage(0);

        // odd iter: compute stage 1, prefetch kk+2 -> stage 0
        asm volatile("cp.async.wait_group 0;\n");
        __syncthreads();
        if (kk + 2 < KITER) prefetch_stage(sb, 0, (kk + 2) * BK, tid, tc);
        else asm volatile("cp.async.commit_group;\n");   // keep group count aligned
        compute_stage(1);
    }

    // ---- epilogue (unpack f16 acc on the fly) ----
    // acc reg h: {row qr+8h, col qc}, {row qr+8h, col qc+1}
    // row-argmax (rows i0..i0+127 over cols j0..j0+127)
#pragma unroll
    for (int mt = 0; mt < 4; mt++) {
#pragma unroll
        for (int h = 0; h < 2; h++) {
            const int mrow = wr * 64 + mt * 16 + qr + 8 * h;
            unsigned long long b = 0ULL;
            if (diag) {
                const int igrp = (i0 + mrow) >> 2;
#pragma unroll
                for (int nt = 0; nt < 4; nt++) {
                    const float2 p = __half22float2(
                        *reinterpret_cast<__half2*>(&acc[mt][nt][h]));
                    const int jg = j0 + wc * 32 + nt * 8 + qc;
                    if ((jg >> 2) != igrp) {           // qc,qc+1 same group of 4
                        b = umax64(b, packmax(p.x, jg));
                        b = umax64(b, packmax(p.y, jg + 1));
                    }
                }
            } else {
#pragma unroll
                for (int nt = 0; nt < 4; nt++) {
                    const float2 p = __half22float2(
                        *reinterpret_cast<__half2*>(&acc[mt][nt][h]));
                    const int jg = j0 + wc * 32 + nt * 8 + qc;
                    b = umax64(b, packmax(p.x, jg));
                    b = umax64(b, packmax(p.y, jg + 1));
                }
            }
            b = umax64(b, __shfl_xor_sync(0xFFFFFFFFu, b, 1));
            b = umax64(b, __shfl_xor_sync(0xFFFFFFFFu, b, 2));
            if ((lane & 3) == 0) atomicMax(&rowbest_s[mrow], b);
        }
    }

    // col-argmax (cols j0..j0+127 over rows i0..i0+127); sim[j][i] by symmetry.
    if (!diag) {
#pragma unroll
        for (int nt = 0; nt < 4; nt++) {
#pragma unroll
            for (int c = 0; c < 2; c++) {
                unsigned long long b = 0ULL;
#pragma unroll
                for (int mt = 0; mt < 4; mt++)
#pragma unroll
                    for (int h = 0; h < 2; h++) {
                        const __half2 hv = *reinterpret_cast<__half2*>(&acc[mt][nt][h]);
                        const float v = (c == 0) ? __low2float(hv) : __high2float(hv);
                        const int ig = i0 + wr * 64 + mt * 16 + qr + 8 * h;
                        b = umax64(b, packmax(v, ig));
                    }
                b = umax64(b, __shfl_xor_sync(0xFFFFFFFFu, b, 4));
                b = umax64(b, __shfl_xor_sync(0xFFFFFFFFu, b, 8));
                b = umax64(b, __shfl_xor_sync(0xFFFFFFFFu, b, 16));
                if (lane < 4)
                    atomicMax(&colbest_s[wc * 32 + nt * 8 + qc + c], b);
            }
        }
    }
    __syncthreads();
    if (tid < 128) {
        atomicMax(&g_best[i0 + tid], rowbest_s[tid]);
        if (!diag) atomicMax(&g_best[j0 + tid], colbest_s[tid]);
    }
}

// ---------------------------------------------------------------------------
// Kernel 3: d_an gather + weighted ratio sum (float4 vectorized, exact fp32)
// ---------------------------------------------------------------------------
__global__ void finalize_kernel(const float* __restrict__ x, float* out) {
    const int i = blockIdx.x;
    const unsigned jg = ~(unsigned)(g_best[i] & 0xFFFFFFFFULL);
    const float4* xi = reinterpret_cast<const float4*>(x + (size_t)i * DIM);
    const float4* xj = reinterpret_cast<const float4*>(x + (size_t)jg * DIM);

    float s = 0.0f;
    for (int d = threadIdx.x; d < DIM / 4; d += 256) {
        const float4 a = xi[d], b = xj[d];
        s += fabsf(a.x - b.x) + fabsf(a.y - b.y) + fabsf(a.z - b.z) + fabsf(a.w - b.w);
    }
#pragma unroll
    for (int o = 16; o > 0; o >>= 1)
        s += __shfl_xor_sync(0xFFFFFFFFu, s, o);

    __shared__ float sw[8];
    if ((threadIdx.x & 31) == 0) sw[threadIdx.x >> 5] = s;
    __syncthreads();
    if (threadIdx.x == 0) {
        float tot = 0.0f;
#pragma unroll
        for (int w = 0; w < 8; w++) tot += sw[w];
        const float dan = tot / (float)DIM;
        atomicAdd(out, 0.125f * g_dap[i] / (dan + 1e-7f));
    }
}

// ---------------------------------------------------------------------------
extern "C" void kernel_launch(void* const* d_in, const int* in_sizes, int n_in,
                              void* d_out, int out_size) {
    const float* x = (const float*)d_in[0];
    float* out = (float*)d_out;

    static bool attr_set = false;
    if (!attr_set) {
        cudaFuncSetAttribute(simgemm_kernel,
                             cudaFuncAttributeMaxDynamicSharedMemorySize, SMEM_BYTES);
        attr_set = true;
    }

    prep_kernel<<<NROWS / CS, 512>>>(x, out);
    simgemm_kernel<<<NPAIR, 256, SMEM_BYTES>>>();
    finalize_kernel<<<NROWS, 256>>>(x, out);
}